// round 13
// baseline (speedup 1.0000x reference)
#include <cuda_runtime.h>
#include <cstdint>

// Problem constants
#define NB     32
#define TT     4096
#define ENC_H  512
#define ATT_H  256
#define OUTD   80
#define SPK    64
#define KW     31
#define NWMAX  19
#define GRID   256

// Device scratch (zero-init; self-resetting per call)
__device__ unsigned bar_cnt = 0;
__device__ unsigned bar_gen = 0;                 // monotonic across replays
__device__ unsigned d_cnt2  = 0;                 // prenet2 producer counter
__device__ unsigned d_count[NB];
__device__ float    d_bias0[NB][ATT_H];
__device__ float    d_h[1024][NB];               // prenet layer-1, k-major
__device__ float    d_p2part[16][NB][512];       // prenet layer-2 split-K partials
__device__ float    d_logit_part[NB][NWMAX][8];
__device__ float    d_Wt[ATT_H][ENC_H];          // W_enc transposed [c][k] (phase A)

// grid-wide sense barrier (all GRID blocks co-resident: 2 blocks/SM)
__device__ __forceinline__ void grid_sync()
{
    __syncthreads();
    if (threadIdx.x == 0) {
        volatile unsigned* vg = &bar_gen;
        unsigned gen = *vg;
        __threadfence();
        if (atomicAdd(&bar_cnt, 1u) == GRID - 1) {
            bar_cnt = 0;
            __threadfence();
            atomicAdd(&bar_gen, 1u);
        } else {
            while (*vg == gen) { __nanosleep(32); }
        }
        __threadfence();
    }
    __syncthreads();
}

struct __align__(16) Smem {
    // enc window 19 x 512, row stride 516 floats (2064B, 16B-aligned).
    // Aliased AFTER all matvec reads as red[t][w][c]: t*516 + w*33 + c (max 9550).
    float enc[NWMAX * 516];                      // 39,216 B (dedicated: cp.async target)
    union {
        float dec_s[8][145];                     // phase A prenet1 inputs
        struct {
            float p_s[512];
            float bias_red[8][33];
            float convw[32 * KW];
            float bias_s[32], benc[32], wproj[32];
        } t;                                     // phase C small
    } v;
    float pa_s[NWMAX + 30 + 3];
    float wv[8]; int wi_[8];
    int sh_lo, sh_nwin, last_s;
};

__global__ __launch_bounds__(256, 2) void k_fused(
    const float* __restrict__ input_enc,
    const float* __restrict__ input_dec,
    const float* __restrict__ prev_att,
    const float* __restrict__ spkr,
    const int*   __restrict__ lengths,
    const float* __restrict__ speed,
    const float* __restrict__ W_enc,
    const float* __restrict__ b_enc,
    const float* __restrict__ W_spkr,
    const float* __restrict__ conv_w,
    const float* __restrict__ W_dec,
    const float* __restrict__ W_speed,
    const float* __restrict__ Wp1,
    const float* __restrict__ bp1,
    const float* __restrict__ Wp2,
    const float* __restrict__ bp2,
    const float* __restrict__ W_proj,
    float* __restrict__ out)
{
    __shared__ Smem sm;
    const int tid  = threadIdx.x;
    const int blk  = blockIdx.x;
    const int b    = blk >> 3;
    const int cg   = blk & 7;
    const int c0   = cg * 32;
    const int lane = tid & 31, wrp = tid >> 5;

    // ============================ PHASE A ============================
    if (blk == 0 && tid == 0) d_cnt2 = 0u;
    if (cg == 0 && tid == 0) d_count[b] = 0u;

    // zero this block's output slice (512 floats)
    if (tid < 128)
        ((float4*)(out + (size_t)b * TT + cg * 512))[tid] =
            make_float4(0.f, 0.f, 0.f, 0.f);

    // full argmax of prev_att[b] (local; first max wins)
    {
        const float4* pa4 = (const float4*)(prev_att + (size_t)b * TT);
        float bv = -1.f; int bi = 0;
        #pragma unroll
        for (int j = 0; j < 4; j++) {
            float4 v = pa4[tid * 4 + j];
            int base = tid * 16 + j * 4;
            if (v.x > bv) { bv = v.x; bi = base; }
            if (v.y > bv) { bv = v.y; bi = base + 1; }
            if (v.z > bv) { bv = v.z; bi = base + 2; }
            if (v.w > bv) { bv = v.w; bi = base + 3; }
        }
        #pragma unroll
        for (int o = 16; o > 0; o >>= 1) {
            float ov = __shfl_down_sync(0xffffffffu, bv, o);
            int   oi = __shfl_down_sync(0xffffffffu, bi, o);
            if (ov > bv || (ov == bv && oi < bi)) { bv = ov; bi = oi; }
        }
        if (lane == 0) { sm.wv[wrp] = bv; sm.wi_[wrp] = bi; }
    }
    __syncthreads();
    if (tid == 0) {
        float xv = sm.wv[0]; int xi = sm.wi_[0];
        #pragma unroll
        for (int j = 1; j < 8; j++) {
            float ov = sm.wv[j]; int oi = sm.wi_[j];
            if (ov > xv || (ov == xv && oi < xi)) { xv = ov; xi = oi; }
        }
        int lo = max(xi - 9, 0);
        int hi = min(xi + 9, lengths[b] - 1);
        sm.sh_lo = lo; sm.sh_nwin = hi - lo + 1;
    }
    __syncthreads();
    const int lo = sm.sh_lo, nwin = sm.sh_nwin;

    // issue async enc-window copy NOW (hidden behind prenet + barrier below)
    {
        const float4* enc4 = (const float4*)(input_enc + (size_t)b * TT * ENC_H);
        #pragma unroll
        for (int r = 0; r < 10; r++) {
            int i = tid + r * 256;
            if (i < NWMAX * 128) {
                int t = i >> 7, q = i & 127;
                int row = lo + t; if (row > TT - 1) row = TT - 1;   // clamped; unused t>=nwin
                uint32_t sa = (uint32_t)__cvta_generic_to_shared(&sm.enc[t * 516 + q * 4]);
                const void* ga = &enc4[(size_t)row * 128 + q];
                asm volatile("cp.async.cg.shared.global [%0], [%1], 16;\n" :: "r"(sa), "l"(ga));
            }
        }
        asm volatile("cp.async.commit_group;\n" ::);
    }

    // transpose one W_enc column into d_Wt (consumed by ALL blocks after barrier)
    {
        float a0 = W_enc[(size_t)tid * ATT_H + blk];
        float a1 = W_enc[(size_t)(tid + 256) * ATT_H + blk];
        d_Wt[blk][tid]       = a0;
        d_Wt[blk][tid + 256] = a1;
    }

    // L2 prefetch: W_dec slice + Wp2 slice (consumed after barrier)
    {
        float pf = 0.f;
        if (tid < 128) {
            float4 a = __ldcg(&((const float4*)W_dec)[blk * 128 + tid]);
            pf = a.x + a.y + a.z + a.w;
        }
        // Wp2: 1024x512 floats = 131072 float4; 256 blocks x 512 float4 = full cover
        {
            float4 w0 = __ldcg(&((const float4*)Wp2)[blk * 512 + tid]);
            float4 w1 = __ldcg(&((const float4*)Wp2)[blk * 512 + 256 + tid]);
            pf += w0.x + w1.x;
        }
        asm volatile("" :: "f"(pf));
    }

    // pa halo (needs lo; consumed in the tail)
    for (int i = tid; i < nwin + 30; i += 256) {
        int p = lo - 15 + i;
        sm.pa_s[i] = (p >= 0 && p < TT) ? prev_att[(size_t)b * TT + p] : 0.f;
    }

    // prenet1: channels [c1,c1+16) x batches [b0,b0+8); Wp1 direct from global
    {
        const int c1 = (blk & 63) * 16;
        const int b0 = (blk >> 6) * 8;
        for (int i = tid; i < 8 * 144; i += 256) {
            int bb = i / 144, k = i - bb * 144;
            sm.v.dec_s[bb][k] = (k < OUTD) ? input_dec[(b0 + bb) * OUTD + k]
                                           : spkr[(b0 + bb) * SPK + (k - OUTD)];
        }
        __syncthreads();
        const int bb = tid >> 5, cc = (tid >> 1) & 15, ss = tid & 1;
        float acc = 0.f;
        #pragma unroll 24
        for (int k = ss * 72; k < ss * 72 + 72; k++)
            acc = fmaf(sm.v.dec_s[bb][k], Wp1[k * 1024 + c1 + cc], acc);
        acc += __shfl_xor_sync(0xffffffffu, acc, 1);
        if (ss == 0)
            d_h[c1 + cc][b0 + bb] = fmaxf(acc + bp1[c1 + cc], 0.f);
    }

    // cg==0 block: spkr softsign + speed bias
    if (cg == 0) {
        float sa = 0.f;
        #pragma unroll 8
        for (int k = 0; k < SPK; k++)
            sa = fmaf(spkr[b * SPK + k], W_spkr[k * ATT_H + tid], sa);
        float v = sa / (1.f + fabsf(sa));
        d_bias0[b][tid] = fmaf(speed[b], W_speed[tid], v);
    }

    grid_sync();                             // d_h, d_bias0, d_Wt visible; dec_s dead

    // stage conv weights / small vectors (union region now phase-C)
    for (int i = tid; i < 32 * KW; i += 256) sm.v.t.convw[i] = conv_w[c0 * KW + i];
    if (tid < 32) {
        sm.v.t.benc[tid]  = b_enc[c0 + tid];
        sm.v.t.wproj[tid] = W_proj[c0 + tid];
    }

    // ============ PHASE B: prenet2 slice (global-direct, full unroll) ============
    {
        const int cb = (blk & 15) * 32;
        const int k0 = (blk >> 4) * 64;
        const int bb = tid & 31;
        const int s  = tid >> 5;
        float4 acc = make_float4(0.f, 0.f, 0.f, 0.f);
        #pragma unroll
        for (int kk = 0; kk < 64; kk++) {
            float hv = __ldcg(&d_h[k0 + kk][bb]);                           // coalesced
            float4 w = *(const float4*)&Wp2[(size_t)(k0 + kk) * 512 + cb + s * 4]; // bcast
            acc.x = fmaf(hv, w.x, acc.x);
            acc.y = fmaf(hv, w.y, acc.y);
            acc.z = fmaf(hv, w.z, acc.z);
            acc.w = fmaf(hv, w.w, acc.w);
        }
        *(float4*)&d_p2part[blk >> 4][bb][cb + s * 4] = acc;
    }
    __threadfence();
    __syncthreads();
    if (tid == 0) atomicAdd(&d_cnt2, 1u);

    // ============================ PHASE C: window ============================
    // enc data: cp.async issued in phase A; wait and sync
    asm volatile("cp.async.wait_group 0;\n" ::);
    __syncthreads();

    // enc matvec (FFMA2, weights pre-packed via d_Wt transpose):
    // cl = tid&15 -> channels c0+cl, c0+cl+16; kq = tid>>4 (16 splits of 32 k)
    const int cl  = tid & 15;
    const int kq  = tid >> 4;
    const int ca  = c0 + cl;
    const int cb2 = c0 + cl + 16;

    unsigned long long acc_a[NWMAX], acc_b[NWMAX];
    #pragma unroll
    for (int t = 0; t < NWMAX; t++) { acc_a[t] = 0ull; acc_b[t] = 0ull; }

    #pragma unroll
    for (int k4 = 0; k4 < 8; k4++) {
        const int kk = kq * 32 + k4 * 4;
        // 4 consecutive k weights, already packed as 2 x f32x2
        ulonglong2 wa = *(const ulonglong2*)&d_Wt[ca][kk];      // LDG.128
        ulonglong2 wb = *(const ulonglong2*)&d_Wt[cb2][kk];     // LDG.128
        #pragma unroll
        for (int t = 0; t < NWMAX; t++) {
            ulonglong2 e = *(const ulonglong2*)&sm.enc[t * 516 + kk];   // LDS.128 bcast
            asm("fma.rn.f32x2 %0,%1,%2,%0;" : "+l"(acc_a[t]) : "l"(e.x), "l"(wa.x));
            asm("fma.rn.f32x2 %0,%1,%2,%0;" : "+l"(acc_a[t]) : "l"(e.y), "l"(wa.y));
            asm("fma.rn.f32x2 %0,%1,%2,%0;" : "+l"(acc_b[t]) : "l"(e.x), "l"(wb.x));
            asm("fma.rn.f32x2 %0,%1,%2,%0;" : "+l"(acc_b[t]) : "l"(e.y), "l"(wb.y));
        }
    }
    __syncthreads();                        // all enc reads done -> region becomes red

    // reduce packed pairs, combine the two kq halves within each warp
    #pragma unroll
    for (int t = 0; t < NWMAX; t++) {
        float l0, h0, l1, h1;
        asm("mov.b64 {%0,%1},%2;" : "=f"(l0), "=f"(h0) : "l"(acc_a[t]));
        asm("mov.b64 {%0,%1},%2;" : "=f"(l1), "=f"(h1) : "l"(acc_b[t]));
        float fa = l0 + h0, fb = l1 + h1;
        float va = fa + __shfl_xor_sync(0xffffffffu, fa, 16);
        float vb = fb + __shfl_xor_sync(0xffffffffu, fb, 16);
        if (lane < 16) {
            sm.enc[t * 516 + wrp * 33 + cl]      = va;
            sm.enc[t * 516 + wrp * 33 + cl + 16] = vb;
        }
    }

    // wait for prenet2 producers (overlapped with matvec; usually already done)
    if (tid == 0) {
        volatile unsigned* vc = &d_cnt2;
        while (*vc < GRID) { __nanosleep(32); }
    }
    __syncthreads();
    __threadfence();

    // reconstruct pout = relu(bp2 + sum of 16 split-K partials)
    #pragma unroll
    for (int r = 0; r < 2; r++) {
        int k = tid + r * 256;
        float v = bp2[k];
        #pragma unroll
        for (int j = 0; j < 16; j++) v += __ldcg(&d_p2part[j][b][k]);
        sm.v.t.p_s[k] = fmaxf(v, 0.f);
    }
    __syncthreads();

    // bias slice: pout @ W_dec[:, c0..c0+32) + bias0  (full unroll for MLP)
    {
        const int cl2 = tid & 31, kq2 = tid >> 5;
        float acc = 0.f;
        #pragma unroll
        for (int j = 0; j < 64; j++) {
            int k = kq2 * 64 + j;
            acc = fmaf(sm.v.t.p_s[k], W_dec[k * ATT_H + c0 + cl2], acc);
        }
        sm.v.t.bias_red[kq2][cl2] = acc;
    }
    __syncthreads();
    if (tid < 32) {
        float s = d_bias0[b][c0 + tid];
        #pragma unroll
        for (int q = 0; q < 8; q++) s += sm.v.t.bias_red[q][tid];
        sm.v.t.bias_s[tid] = s;
    }
    __syncthreads();

    // parallel tail: warp wrp handles t = p*8 + wrp
    #pragma unroll
    for (int p = 0; p < 3; p++) {
        const int t = p * 8 + wrp;
        float v = 0.f;
        if (t < nwin) {
            float s = 0.f;
            #pragma unroll
            for (int q = 0; q < 8; q++) s += sm.enc[t * 516 + q * 33 + lane];
            s += sm.v.t.benc[lane];
            s = s / (1.f + fabsf(s));                   // softsign(enc@W_enc + b_enc)
            s += sm.v.t.bias_s[lane];
            float cv = 0.f;
            #pragma unroll
            for (int j = 0; j < KW; j++)
                cv = fmaf(sm.pa_s[t + j], sm.v.t.convw[lane * KW + j], cv);
            s += cv;
            v = tanhf(s) * sm.v.t.wproj[lane];
        }
        #pragma unroll
        for (int o = 16; o > 0; o >>= 1) v += __shfl_down_sync(0xffffffffu, v, o);
        if (lane == 0 && t < nwin) d_logit_part[b][t][cg] = v;
    }

    // last-block-done fused softmax
    __threadfence();
    __syncthreads();
    if (tid == 0) {
        unsigned old = atomicAdd(&d_count[b], 1u);
        sm.last_s = (old == 7u) ? 1 : 0;
    }
    __syncthreads();
    if (sm.last_s && tid < 32) {
        const int t = tid;
        float lg = -1e30f;
        if (t < nwin) {
            float s = 0.f;
            #pragma unroll
            for (int q = 0; q < 8; q++) s += __ldcg(&d_logit_part[b][t][q]);
            lg = s;
        }
        float m = lg;
        #pragma unroll
        for (int o = 16; o > 0; o >>= 1) m = fmaxf(m, __shfl_xor_sync(0xffffffffu, m, o));
        float e = (t < nwin) ? expf(lg - m) : 0.f;
        float sum = e;
        #pragma unroll
        for (int o = 16; o > 0; o >>= 1) sum += __shfl_xor_sync(0xffffffffu, sum, o);
        if (t < nwin) out[(size_t)b * TT + lo + t] = e / sum;
    }
}

// ---------------------------------------------------------------------------
extern "C" void kernel_launch(void* const* d_in, const int* in_sizes, int n_in,
                              void* d_out, int out_size)
{
    const float* input_enc = (const float*)d_in[0];
    const float* input_dec = (const float*)d_in[1];
    const float* prev_att  = (const float*)d_in[2];
    const float* spkr      = (const float*)d_in[3];
    const int*   lengths   = (const int*)  d_in[4];
    const float* speed     = (const float*)d_in[5];
    const float* W_enc     = (const float*)d_in[6];
    const float* b_enc     = (const float*)d_in[7];
    const float* W_spkr    = (const float*)d_in[8];
    const float* conv_w    = (const float*)d_in[9];
    const float* W_dec     = (const float*)d_in[10];
    const float* W_speed   = (const float*)d_in[11];
    const float* Wp1       = (const float*)d_in[12];
    const float* bp1       = (const float*)d_in[13];
    const float* Wp2       = (const float*)d_in[14];
    const float* bp2       = (const float*)d_in[15];
    const float* W_proj    = (const float*)d_in[16];
    // d_in[17] = b_proj: constant shift, cancels in the masked softmax.

    k_fused<<<GRID, 256>>>(input_enc, input_dec, prev_att, spkr, lengths, speed,
                           W_enc, b_enc, W_spkr, conv_w, W_dec, W_speed,
                           Wp1, bp1, Wp2, bp2, W_proj, (float*)d_out);
}

// round 14
// speedup vs baseline: 1.1466x; 1.1466x over previous
#include <cuda_runtime.h>
#include <cstdint>

// Problem constants
#define NB     32
#define TT     4096
#define ENC_H  512
#define ATT_H  256
#define OUTD   80
#define SPK    64
#define KW     31
#define NWMAX  19
#define GRID   256

// Device scratch (zero-init; self-resetting per call)
__device__ unsigned bar_cnt = 0;
__device__ unsigned bar_gen = 0;                 // monotonic across replays
__device__ unsigned d_cnt2  = 0;                 // prenet2 producer counter
__device__ unsigned d_count[NB];
__device__ float    d_h[1024][NB];               // prenet layer-1, k-major
__device__ float    d_p2part[16][NB][512];       // prenet layer-2 split-K partials
__device__ float    d_logit_part[NB][NWMAX][8];

// grid-wide sense barrier (all GRID blocks co-resident: 2 blocks/SM)
__device__ __forceinline__ void grid_sync()
{
    __syncthreads();
    if (threadIdx.x == 0) {
        volatile unsigned* vg = &bar_gen;
        unsigned gen = *vg;
        __threadfence();
        if (atomicAdd(&bar_cnt, 1u) == GRID - 1) {
            bar_cnt = 0;
            __threadfence();
            atomicAdd(&bar_gen, 1u);
        } else {
            while (*vg == gen) { __nanosleep(32); }
        }
        __threadfence();
    }
    __syncthreads();
}

struct __align__(16) Smem {
    // enc window 19 x 512, row stride 516 floats (2064B, 16B-aligned).
    // Aliased AFTER all matvec reads as red[t][w][c]: t*516 + w*33 + c (max 9550).
    float enc[NWMAX * 516];                      // 39,216 B (dedicated: cp.async target)
    union {
        float dec_s[8][145];                     // phase A prenet1 inputs
        struct {
            float p_s[512];
            float bias_red[8][33];
            float convw[32 * KW];
            float bias_s[32], benc[32], wproj[32];
        } t;                                     // phase C small
    } v;
    float pa_s[NWMAX + 30 + 3];
    float wv[8]; int wi_[8];
    int sh_lo, sh_nwin, last_s;
};

__global__ __launch_bounds__(256, 2) void k_fused(
    const float* __restrict__ input_enc,
    const float* __restrict__ input_dec,
    const float* __restrict__ prev_att,
    const float* __restrict__ spkr,
    const int*   __restrict__ lengths,
    const float* __restrict__ speed,
    const float* __restrict__ W_enc,
    const float* __restrict__ b_enc,
    const float* __restrict__ W_spkr,
    const float* __restrict__ conv_w,
    const float* __restrict__ W_dec,
    const float* __restrict__ W_speed,
    const float* __restrict__ Wp1,
    const float* __restrict__ bp1,
    const float* __restrict__ Wp2,
    const float* __restrict__ bp2,
    const float* __restrict__ W_proj,
    float* __restrict__ out)
{
    __shared__ Smem sm;
    const int tid  = threadIdx.x;
    const int blk  = blockIdx.x;
    const int b    = blk >> 3;
    const int cg   = blk & 7;
    const int c0   = cg * 32;
    const int lane = tid & 31, wrp = tid >> 5;

    // ============================ PHASE A ============================
    if (blk == 0 && tid == 0) d_cnt2 = 0u;
    if (cg == 0 && tid == 0) d_count[b] = 0u;

    // zero this block's output slice (512 floats)
    if (tid < 128)
        ((float4*)(out + (size_t)b * TT + cg * 512))[tid] =
            make_float4(0.f, 0.f, 0.f, 0.f);

    // full argmax of prev_att[b] (local; first max wins)
    {
        const float4* pa4 = (const float4*)(prev_att + (size_t)b * TT);
        float bv = -1.f; int bi = 0;
        #pragma unroll
        for (int j = 0; j < 4; j++) {
            float4 v = pa4[tid * 4 + j];
            int base = tid * 16 + j * 4;
            if (v.x > bv) { bv = v.x; bi = base; }
            if (v.y > bv) { bv = v.y; bi = base + 1; }
            if (v.z > bv) { bv = v.z; bi = base + 2; }
            if (v.w > bv) { bv = v.w; bi = base + 3; }
        }
        #pragma unroll
        for (int o = 16; o > 0; o >>= 1) {
            float ov = __shfl_down_sync(0xffffffffu, bv, o);
            int   oi = __shfl_down_sync(0xffffffffu, bi, o);
            if (ov > bv || (ov == bv && oi < bi)) { bv = ov; bi = oi; }
        }
        if (lane == 0) { sm.wv[wrp] = bv; sm.wi_[wrp] = bi; }
    }
    __syncthreads();
    if (tid == 0) {
        float xv = sm.wv[0]; int xi = sm.wi_[0];
        #pragma unroll
        for (int j = 1; j < 8; j++) {
            float ov = sm.wv[j]; int oi = sm.wi_[j];
            if (ov > xv || (ov == xv && oi < xi)) { xv = ov; xi = oi; }
        }
        int lo = max(xi - 9, 0);
        int hi = min(xi + 9, lengths[b] - 1);
        sm.sh_lo = lo; sm.sh_nwin = hi - lo + 1;
    }
    __syncthreads();
    const int lo = sm.sh_lo, nwin = sm.sh_nwin;

    // issue async enc-window copy NOW (hidden behind prenet + barrier below)
    {
        const float4* enc4 = (const float4*)(input_enc + (size_t)b * TT * ENC_H);
        #pragma unroll
        for (int r = 0; r < 10; r++) {
            int i = tid + r * 256;
            if (i < NWMAX * 128) {
                int t = i >> 7, q = i & 127;
                int row = lo + t; if (row > TT - 1) row = TT - 1;   // clamped; unused t>=nwin
                uint32_t sa = (uint32_t)__cvta_generic_to_shared(&sm.enc[t * 516 + q * 4]);
                const void* ga = &enc4[(size_t)row * 128 + q];
                asm volatile("cp.async.cg.shared.global [%0], [%1], 16;\n" :: "r"(sa), "l"(ga));
            }
        }
        asm volatile("cp.async.commit_group;\n" ::);
    }

    // L2 prefetch: W_enc slice + Wp2 slice + W_dec slice (consumed after barrier)
    {
        float pf = 0.f;
        if (tid < 128) {
            float4 a = __ldcg(&((const float4*)W_enc)[blk * 128 + tid]);
            float4 d = __ldcg(&((const float4*)W_dec)[blk * 128 + tid]);
            pf = a.x + a.y + d.x + d.w;
        }
        // Wp2: 1024x512 floats = 131072 float4; 256 blocks x 512 float4 = full cover
        {
            float4 w0 = __ldcg(&((const float4*)Wp2)[blk * 512 + tid]);
            float4 w1 = __ldcg(&((const float4*)Wp2)[blk * 512 + 256 + tid]);
            pf += w0.x + w1.x;
        }
        asm volatile("" :: "f"(pf));
    }

    // pa halo (needs lo; consumed in the tail)
    for (int i = tid; i < nwin + 30; i += 256) {
        int p = lo - 15 + i;
        sm.pa_s[i] = (p >= 0 && p < TT) ? prev_att[(size_t)b * TT + p] : 0.f;
    }

    // prenet1: channels [c1,c1+16) x batches [b0,b0+8); Wp1 direct from global
    {
        const int c1 = (blk & 63) * 16;
        const int b0 = (blk >> 6) * 8;
        for (int i = tid; i < 8 * 144; i += 256) {
            int bb = i / 144, k = i - bb * 144;
            sm.v.dec_s[bb][k] = (k < OUTD) ? input_dec[(b0 + bb) * OUTD + k]
                                           : spkr[(b0 + bb) * SPK + (k - OUTD)];
        }
        __syncthreads();
        const int bb = tid >> 5, cc = (tid >> 1) & 15, ss = tid & 1;
        float acc = 0.f;
        #pragma unroll 24
        for (int k = ss * 72; k < ss * 72 + 72; k++)
            acc = fmaf(sm.v.dec_s[bb][k], Wp1[k * 1024 + c1 + cc], acc);
        acc += __shfl_xor_sync(0xffffffffu, acc, 1);
        if (ss == 0)
            d_h[c1 + cc][b0 + bb] = fmaxf(acc + bp1[c1 + cc], 0.f);
    }

    grid_sync();                             // d_h visible; dec_s dead

    // stage conv weights / small vectors (union region now phase-C)
    for (int i = tid; i < 32 * KW; i += 256) sm.v.t.convw[i] = conv_w[c0 * KW + i];
    if (tid < 32) {
        sm.v.t.benc[tid]  = b_enc[c0 + tid];
        sm.v.t.wproj[tid] = W_proj[c0 + tid];
    }

    // ============ PHASE B: prenet2 slice (global-direct, full unroll) ============
    {
        const int cb = (blk & 15) * 32;
        const int k0 = (blk >> 4) * 64;
        const int bb = tid & 31;
        const int s  = tid >> 5;
        float4 acc = make_float4(0.f, 0.f, 0.f, 0.f);
        #pragma unroll
        for (int kk = 0; kk < 64; kk++) {
            float hv = __ldcg(&d_h[k0 + kk][bb]);                           // coalesced
            float4 w = *(const float4*)&Wp2[(size_t)(k0 + kk) * 512 + cb + s * 4]; // bcast
            acc.x = fmaf(hv, w.x, acc.x);
            acc.y = fmaf(hv, w.y, acc.y);
            acc.z = fmaf(hv, w.z, acc.z);
            acc.w = fmaf(hv, w.w, acc.w);
        }
        *(float4*)&d_p2part[blk >> 4][bb][cb + s * 4] = acc;
    }
    __threadfence();
    __syncthreads();
    if (tid == 0) atomicAdd(&d_cnt2, 1u);

    // ============================ PHASE C: window ============================
    // enc data: cp.async issued in phase A; wait and sync
    asm volatile("cp.async.wait_group 0;\n" ::);
    __syncthreads();

    // enc matvec (FFMA2 over packed k-pairs):
    // cl = tid&15 -> channels c0+cl, c0+cl+16; kq = tid>>4 (16 splits of 32 k)
    const int cl  = tid & 15;
    const int kq  = tid >> 4;
    const int ca  = c0 + cl;
    const int cb2 = c0 + cl + 16;

    unsigned long long acc_a[NWMAX], acc_b[NWMAX];
    #pragma unroll
    for (int t = 0; t < NWMAX; t++) { acc_a[t] = 0ull; acc_b[t] = 0ull; }

    #pragma unroll
    for (int k4 = 0; k4 < 8; k4++) {
        const int kk = kq * 32 + k4 * 4;
        float w0a = W_enc[(kk + 0) * ATT_H + ca];
        float w1a = W_enc[(kk + 1) * ATT_H + ca];
        float w2a = W_enc[(kk + 2) * ATT_H + ca];
        float w3a = W_enc[(kk + 3) * ATT_H + ca];
        float w0b = W_enc[(kk + 0) * ATT_H + cb2];
        float w1b = W_enc[(kk + 1) * ATT_H + cb2];
        float w2b = W_enc[(kk + 2) * ATT_H + cb2];
        float w3b = W_enc[(kk + 3) * ATT_H + cb2];
        unsigned long long wa01, wa23, wb01, wb23;
        asm("mov.b64 %0,{%1,%2};" : "=l"(wa01) : "f"(w0a), "f"(w1a));
        asm("mov.b64 %0,{%1,%2};" : "=l"(wa23) : "f"(w2a), "f"(w3a));
        asm("mov.b64 %0,{%1,%2};" : "=l"(wb01) : "f"(w0b), "f"(w1b));
        asm("mov.b64 %0,{%1,%2};" : "=l"(wb23) : "f"(w2b), "f"(w3b));
        #pragma unroll
        for (int t = 0; t < NWMAX; t++) {
            ulonglong2 e = *(const ulonglong2*)&sm.enc[t * 516 + kk];   // LDS.128 bcast
            asm("fma.rn.f32x2 %0,%1,%2,%0;" : "+l"(acc_a[t]) : "l"(e.x), "l"(wa01));
            asm("fma.rn.f32x2 %0,%1,%2,%0;" : "+l"(acc_a[t]) : "l"(e.y), "l"(wa23));
            asm("fma.rn.f32x2 %0,%1,%2,%0;" : "+l"(acc_b[t]) : "l"(e.x), "l"(wb01));
            asm("fma.rn.f32x2 %0,%1,%2,%0;" : "+l"(acc_b[t]) : "l"(e.y), "l"(wb23));
        }
    }
    __syncthreads();                        // all enc reads done -> region becomes red

    // reduce packed pairs, combine the two kq halves within each warp
    #pragma unroll
    for (int t = 0; t < NWMAX; t++) {
        float l0, h0, l1, h1;
        asm("mov.b64 {%0,%1},%2;" : "=f"(l0), "=f"(h0) : "l"(acc_a[t]));
        asm("mov.b64 {%0,%1},%2;" : "=f"(l1), "=f"(h1) : "l"(acc_b[t]));
        float fa = l0 + h0, fb = l1 + h1;
        float va = fa + __shfl_xor_sync(0xffffffffu, fa, 16);
        float vb = fb + __shfl_xor_sync(0xffffffffu, fb, 16);
        if (lane < 16) {
            sm.enc[t * 516 + wrp * 33 + cl]      = va;
            sm.enc[t * 516 + wrp * 33 + cl + 16] = vb;
        }
    }

    // bias0 (spkr softsign + speed) in registers of tid<32 — its DRAM latency
    // hides behind the cnt2 spin below (independent of pout)
    float sb0 = 0.f;
    if (tid < 32) {
        float sa = 0.f;
        #pragma unroll
        for (int k = 0; k < SPK; k++)
            sa = fmaf(spkr[b * SPK + k], W_spkr[k * ATT_H + c0 + tid], sa);
        sb0 = sa / (1.f + fabsf(sa));
        sb0 = fmaf(speed[b], W_speed[c0 + tid], sb0);
    }

    // wait for prenet2 producers (overlapped with matvec; usually already done)
    if (tid == 0) {
        volatile unsigned* vc = &d_cnt2;
        while (*vc < GRID) { __nanosleep(32); }
    }
    __syncthreads();
    __threadfence();

    // reconstruct pout = relu(bp2 + sum of 16 split-K partials)
    #pragma unroll
    for (int r = 0; r < 2; r++) {
        int k = tid + r * 256;
        float v = bp2[k];
        #pragma unroll
        for (int j = 0; j < 16; j++) v += __ldcg(&d_p2part[j][b][k]);
        sm.v.t.p_s[k] = fmaxf(v, 0.f);
    }
    __syncthreads();

    // bias slice: pout @ W_dec[:, c0..c0+32) + bias0  (full unroll for MLP)
    {
        const int cl2 = tid & 31, kq2 = tid >> 5;
        float acc = 0.f;
        #pragma unroll
        for (int j = 0; j < 64; j++) {
            int k = kq2 * 64 + j;
            acc = fmaf(sm.v.t.p_s[k], W_dec[k * ATT_H + c0 + cl2], acc);
        }
        sm.v.t.bias_red[kq2][cl2] = acc;
    }
    __syncthreads();
    if (tid < 32) {
        float s = sb0;
        #pragma unroll
        for (int q = 0; q < 8; q++) s += sm.v.t.bias_red[q][tid];
        sm.v.t.bias_s[tid] = s;
    }
    __syncthreads();

    // parallel tail: warp wrp handles t = p*8 + wrp
    #pragma unroll
    for (int p = 0; p < 3; p++) {
        const int t = p * 8 + wrp;
        float v = 0.f;
        if (t < nwin) {
            float s = 0.f;
            #pragma unroll
            for (int q = 0; q < 8; q++) s += sm.enc[t * 516 + q * 33 + lane];
            s += sm.v.t.benc[lane];
            s = s / (1.f + fabsf(s));                   // softsign(enc@W_enc + b_enc)
            s += sm.v.t.bias_s[lane];
            float cv = 0.f;
            #pragma unroll
            for (int j = 0; j < KW; j++)
                cv = fmaf(sm.pa_s[t + j], sm.v.t.convw[lane * KW + j], cv);
            s += cv;
            v = tanhf(s) * sm.v.t.wproj[lane];
        }
        #pragma unroll
        for (int o = 16; o > 0; o >>= 1) v += __shfl_down_sync(0xffffffffu, v, o);
        if (lane == 0 && t < nwin) d_logit_part[b][t][cg] = v;
    }

    // last-block-done fused softmax
    __threadfence();
    __syncthreads();
    if (tid == 0) {
        unsigned old = atomicAdd(&d_count[b], 1u);
        sm.last_s = (old == 7u) ? 1 : 0;
    }
    __syncthreads();
    if (sm.last_s && tid < 32) {
        const int t = tid;
        float lg = -1e30f;
        if (t < nwin) {
            float s = 0.f;
            #pragma unroll
            for (int q = 0; q < 8; q++) s += __ldcg(&d_logit_part[b][t][q]);
            lg = s;
        }
        float m = lg;
        #pragma unroll
        for (int o = 16; o > 0; o >>= 1) m = fmaxf(m, __shfl_xor_sync(0xffffffffu, m, o));
        float e = (t < nwin) ? expf(lg - m) : 0.f;
        float sum = e;
        #pragma unroll
        for (int o = 16; o > 0; o >>= 1) sum += __shfl_xor_sync(0xffffffffu, sum, o);
        if (t < nwin) out[(size_t)b * TT + lo + t] = e / sum;
    }
}

// ---------------------------------------------------------------------------
extern "C" void kernel_launch(void* const* d_in, const int* in_sizes, int n_in,
                              void* d_out, int out_size)
{
    const float* input_enc = (const float*)d_in[0];
    const float* input_dec = (const float*)d_in[1];
    const float* prev_att  = (const float*)d_in[2];
    const float* spkr      = (const float*)d_in[3];
    const int*   lengths   = (const int*)  d_in[4];
    const float* speed     = (const float*)d_in[5];
    const float* W_enc     = (const float*)d_in[6];
    const float* b_enc     = (const float*)d_in[7];
    const float* W_spkr    = (const float*)d_in[8];
    const float* conv_w    = (const float*)d_in[9];
    const float* W_dec     = (const float*)d_in[10];
    const float* W_speed   = (const float*)d_in[11];
    const float* Wp1       = (const float*)d_in[12];
    const float* bp1       = (const float*)d_in[13];
    const float* Wp2       = (const float*)d_in[14];
    const float* bp2       = (const float*)d_in[15];
    const float* W_proj    = (const float*)d_in[16];
    // d_in[17] = b_proj: constant shift, cancels in the masked softmax.

    k_fused<<<GRID, 256>>>(input_enc, input_dec, prev_att, spkr, lengths, speed,
                           W_enc, b_enc, W_spkr, conv_w, W_dec, W_speed,
                           Wp1, bp1, Wp2, bp2, W_proj, (float*)d_out);
}